// round 9
// baseline (speedup 1.0000x reference)
#include <cuda_runtime.h>
#include <cuda_fp16.h>
#include <cstdint>

// ---------------- problem constants ----------------
#define DIM      4096
#define EXPERTS  64
#define T_TOK    8192
#define MB       64                  // tokens per GEMM block
#define BK       64                  // k per stage
#define NSTAGE   (DIM / BK)          // 64
#define GTH      256                 // 8 warps
#define BT       64
#define NB       (T_TOK / BT)        // 128
#define SUSCAP   2048
#define EPS_GAP  1e-5f

// smem layout in uint32 units (fp16x2 packed), USTR=36 -> conflict-free frags
#define USTR     36
#define OFFU_AH  0
#define OFFU_AM  2304                // 64*36
#define OFFU_WH  4608
#define OFFU_WM  6912
#define BUFU     9216
#define SMEM_BYTES (2 * BUFU * 4)    // 73728 B (also covers 64x65 epi floats)

// ---------------- device scratch ----------------
__device__ float    g_logits[T_TOK * EXPERTS];
__device__ uint32_t g_wh[EXPERTS * (DIM / 2)];   // W hi split, fp16x2
__device__ uint32_t g_wm[EXPERTS * (DIM / 2)];   // W mid split, fp16x2
__device__ float    g_me[EXPERTS];
__device__ int      g_indices[T_TOK];
__device__ int      g_blockCounts[NB * EXPERTS];
__device__ int      g_blockOffsets[NB * EXPERTS];
__device__ int      g_nsus;
__device__ int      g_suspects[SUSCAP];

// ---------------- helpers ----------------
__device__ __forceinline__ uint32_t smem_u32(const void* p) {
    uint32_t a;
    asm("{ .reg .u64 t; cvta.to.shared.u64 t, %1; cvt.u32.u64 %0, t; }" : "=r"(a) : "l"(p));
    return a;
}
// split (x0,x1) fp32 -> hi fp16x2 + mid fp16x2 (captures ~22 mantissa bits)
__device__ __forceinline__ void split_f16x2(float x0, float x1,
                                            uint32_t& h, uint32_t& m) {
    __half2 h2 = __floats2half2_rn(x0, x1);
    h = *reinterpret_cast<uint32_t*>(&h2);
    float r0 = x0 - __low2float(h2);
    float r1 = x1 - __high2float(h2);
    __half2 m2 = __floats2half2_rn(r0, r1);
    m = *reinterpret_cast<uint32_t*>(&m2);
}
__device__ __forceinline__ void cp16(uint32_t saddr, const void* g) {
    asm volatile("cp.async.cg.shared.global [%0], [%1], 16;" :: "r"(saddr), "l"(g));
}
#define CP_COMMIT() asm volatile("cp.async.commit_group;" ::: "memory")
#define CP_WAIT0()  asm volatile("cp.async.wait_group 0;" ::: "memory")

#define MMA_FP16(d, a, b0, b1)                                               \
    asm volatile(                                                            \
        "mma.sync.aligned.m16n8k16.row.col.f32.f16.f16.f32 "                 \
        "{%0,%1,%2,%3}, {%4,%5,%6,%7}, {%8,%9}, {%0,%1,%2,%3};"              \
        : "+f"((d)[0]), "+f"((d)[1]), "+f"((d)[2]), "+f"((d)[3])             \
        : "r"((a)[0]), "r"((a)[1]), "r"((a)[2]), "r"((a)[3]),                \
          "r"(b0), "r"(b1))

// ---------------- pass 0: W split precompute + init ----------------
__global__ void wsplit_kernel(const float* __restrict__ W) {
    int i = blockIdx.x * blockDim.x + threadIdx.x;   // pair index
    if (i < EXPERTS * (DIM / 2)) {
        float2 x = reinterpret_cast<const float2*>(W)[i];
        uint32_t h, m;
        split_f16x2(x.x, x.y, h, m);
        g_wh[i] = h;
        g_wm[i] = m;
    }
    if (i < EXPERTS) g_me[i] = 0.0f;
    if (i == 0) g_nsus = 0;
}

// ---------------- pass 1: fp16-split GEMM + fused gate epilogue -------------
#define ESTR 65
__global__ __launch_bounds__(GTH, 1) void gemm_kernel(
    const float* __restrict__ A, float* __restrict__ out, int T)
{
    extern __shared__ __align__(16) uint32_t smu[];
    const uint32_t sbase = smem_u32(smu);
    const int tid  = threadIdx.x;
    const int lane = tid & 31;
    const int wid  = tid >> 5;       // 8 warps
    const int wm   = wid >> 1;       // 0..3 : 16-token group
    const int wn   = wid & 1;        // 0..1 : 32-expert group
    const int t0   = blockIdx.x * MB;

    float acc[4][4];
#pragma unroll
    for (int ni = 0; ni < 4; ni++)
#pragma unroll
        for (int r = 0; r < 4; r++) acc[ni][r] = 0.0f;

    // prologue: A regs stage 0, W cp.async stage 0
    float4 pA[4];
#pragma unroll
    for (int q = 0; q < 4; q++) {
        int f4 = q * GTH + tid;
        int row = f4 >> 4, c = (f4 & 15) * 4;
        pA[q] = *reinterpret_cast<const float4*>(&A[(size_t)(t0 + row) * DIM + c]);
    }
#pragma unroll
    for (int q = 0; q < 2; q++) {
        int f = q * GTH + tid;               // 0..511
        int row = f >> 3, c = (f & 7) * 4;   // uint32 col
        cp16(sbase + (OFFU_WH + row * USTR + c) * 4, &g_wh[row * (DIM / 2) + c]);
        cp16(sbase + (OFFU_WM + row * USTR + c) * 4, &g_wm[row * (DIM / 2) + c]);
    }
    CP_COMMIT();

    for (int s = 0; s < NSTAGE; s++) {
        uint32_t* buf = smu + (s & 1) * BUFU;
        CP_WAIT0();

        // split-store A tile (fp16 hi/mid)
#pragma unroll
        for (int q = 0; q < 4; q++) {
            int f4 = q * GTH + tid;
            int row = f4 >> 4, c = (f4 & 15) * 4;    // float col
            uint2 h, m;
            split_f16x2(pA[q].x, pA[q].y, h.x, m.x);
            split_f16x2(pA[q].z, pA[q].w, h.y, m.y);
            *reinterpret_cast<uint2*>(&buf[OFFU_AH + row * USTR + c / 2]) = h;
            *reinterpret_cast<uint2*>(&buf[OFFU_AM + row * USTR + c / 2]) = m;
        }
        __syncthreads();

        // prefetch stage s+1
        if (s + 1 < NSTAGE) {
            const int k0 = (s + 1) * BK;
#pragma unroll
            for (int q = 0; q < 4; q++) {
                int f4 = q * GTH + tid;
                int row = f4 >> 4, c = (f4 & 15) * 4;
                pA[q] = *reinterpret_cast<const float4*>(&A[(size_t)(t0 + row) * DIM + k0 + c]);
            }
            uint32_t nb = sbase + ((s + 1) & 1) * BUFU * 4;
            const int ku = k0 / 2;
#pragma unroll
            for (int q = 0; q < 2; q++) {
                int f = q * GTH + tid;
                int row = f >> 3, c = (f & 7) * 4;
                cp16(nb + (OFFU_WH + row * USTR + c) * 4, &g_wh[row * (DIM / 2) + ku + c]);
                cp16(nb + (OFFU_WM + row * USTR + c) * 4, &g_wm[row * (DIM / 2) + ku + c]);
            }
            CP_COMMIT();
        }

        // compute: 4 k16 steps
#pragma unroll
        for (int q = 0; q < 4; q++) {
            const int cu = q * 8 + (lane & 3);
            const int r  = wm * 16 + (lane >> 2);
            uint32_t aH[4], aM[4];
            {
                int b0 = OFFU_AH + r * USTR + cu;
                aH[0] = buf[b0];
                aH[1] = buf[b0 + 8 * USTR];
                aH[2] = buf[b0 + 4];
                aH[3] = buf[b0 + 8 * USTR + 4];
                int b1 = OFFU_AM + r * USTR + cu;
                aM[0] = buf[b1];
                aM[1] = buf[b1 + 8 * USTR];
                aM[2] = buf[b1 + 4];
                aM[3] = buf[b1 + 8 * USTR + 4];
            }
#pragma unroll
            for (int ni = 0; ni < 4; ni++) {
                int n = wn * 32 + ni * 8 + (lane >> 2);
                int bb = n * USTR + cu;
                uint32_t bh0 = buf[OFFU_WH + bb], bh1 = buf[OFFU_WH + bb + 4];
                uint32_t bm0 = buf[OFFU_WM + bb], bm1 = buf[OFFU_WM + bb + 4];
                MMA_FP16(acc[ni], aH, bh0, bh1);
                MMA_FP16(acc[ni], aH, bm0, bm1);
                MMA_FP16(acc[ni], aM, bh0, bh1);
            }
        }
    }

    // ---- fused epilogue ----
    __syncthreads();                       // everyone done reading buffers
    float* epi = reinterpret_cast<float*>(smu);      // [64][65]
#pragma unroll
    for (int ni = 0; ni < 4; ni++) {
        int r0 = wm * 16 + (lane >> 2);
        int c0 = wn * 32 + ni * 8 + (lane & 3) * 2;
        epi[r0 * ESTR + c0]           = acc[ni][0];
        epi[r0 * ESTR + c0 + 1]       = acc[ni][1];
        epi[(r0 + 8) * ESTR + c0]     = acc[ni][2];
        epi[(r0 + 8) * ESTR + c0 + 1] = acc[ni][3];
        // gmem logits (write-only; rescue reads them)
        *reinterpret_cast<float2*>(&g_logits[(size_t)(t0 + r0) * EXPERTS + c0]) =
            make_float2(acc[ni][0], acc[ni][1]);
        *reinterpret_cast<float2*>(&g_logits[(size_t)(t0 + r0 + 8) * EXPERTS + c0]) =
            make_float2(acc[ni][2], acc[ni][3]);
    }
    __shared__ float ms[MB];
    __shared__ float sums[MB];
    __shared__ int   cnt_s[EXPERTS];
    if (tid < EXPERTS) cnt_s[tid] = 0;
    __syncthreads();

    if (tid < MB) {
        const int t = tid;
        float m = epi[t * ESTR + 0];
        float m2 = -3.4e38f;
        int am = 0;
#pragma unroll 4
        for (int e = 1; e < EXPERTS; e++) {
            float v = epi[t * ESTR + e];
            if (v > m) { m2 = m; m = v; am = e; }
            else if (v > m2) { m2 = v; }
        }
        float ssum = 0.0f;
#pragma unroll 4
        for (int e = 0; e < EXPERTS; e++)
            ssum += __expf(epi[t * ESTR + e] - m);
        ms[t] = m;
        sums[t] = ssum;
        int gt = t0 + t;
        g_indices[gt]       = am;
        out[1 + gt]         = (float)am;
        out[1 + 2 * T + gt] = 1.0f / ssum;
        atomicAdd(&cnt_s[am], 1);
        if (m - m2 < EPS_GAP) {
            int i = atomicAdd(&g_nsus, 1);
            if (i < SUSCAP) g_suspects[i] = gt;
        }
    }
    __syncthreads();

    if (tid < EXPERTS) {
        const int e = tid;
        float accm = 0.0f;
#pragma unroll 4
        for (int t = 0; t < MB; t++)
            accm += __expf(epi[t * ESTR + e] - ms[t]) / sums[t];
        atomicAdd(&g_me[e], accm);
        g_blockCounts[blockIdx.x * EXPERTS + e] = cnt_s[e];
    }
}

// ---------------- pass 2: double-single rescue (adjusts counts) --------------
__device__ __forceinline__ void two_sum(float a, float b, float& s, float& e) {
    s = a + b;
    float bb = s - a;
    e = (a - (s - bb)) + (b - bb);
}

__global__ void rescue_kernel(const float* __restrict__ A,
                              const float* __restrict__ W,
                              float* __restrict__ out, int T) {
    __shared__ float Lsm[EXPERTS];
    __shared__ double bv[8];
    __shared__ int    bi[8];
    const int wid = threadIdx.x >> 5;   // 8 warps
    const int lane = threadIdx.x & 31;
    int n = g_nsus;
    if (n > SUSCAP) n = SUSCAP;

    for (int s = blockIdx.x; s < n; s += gridDim.x) {
        const int t = g_suspects[s];
        const float* ap = A + (size_t)t * DIM;

        if (threadIdx.x < EXPERTS)
            Lsm[threadIdx.x] = g_logits[(size_t)t * EXPERTS + threadIdx.x];
        __syncthreads();
        float mx32 = Lsm[0];
        for (int e = 1; e < EXPERTS; e++) mx32 = fmaxf(mx32, Lsm[e]);
        const float win = mx32 - 2.0f * EPS_GAP;

        double best = -1e300;
        int besti = EXPERTS;
#pragma unroll 1
        for (int sub = 0; sub < 8; sub++) {
            const int e = wid * 8 + sub;
            if (Lsm[e] < win) continue;
            const float* wp = W + (size_t)e * DIM;
            float sacc = 0.0f, cacc = 0.0f;
#pragma unroll 4
            for (int i = 0; i < DIM / 128; i++) {
                int k = (i * 32 + lane) * 4;
                float4 av = *reinterpret_cast<const float4*>(ap + k);
                float4 wv = *reinterpret_cast<const float4*>(wp + k);
#pragma unroll
                for (int j = 0; j < 4; j++) {
                    float a = (&av.x)[j], b = (&wv.x)[j];
                    float p = a * b;
                    float pe = fmaf(a, b, -p);
                    float tnew, err;
                    two_sum(sacc, p, tnew, err);
                    cacc += err + pe;
                    sacc = tnew;
                }
            }
#pragma unroll
            for (int o = 16; o; o >>= 1) {
                float sh = __shfl_down_sync(0xffffffffu, sacc, o);
                float ch = __shfl_down_sync(0xffffffffu, cacc, o);
                float tnew, err;
                two_sum(sacc, sh, tnew, err);
                cacc += ch + err;
                sacc = tnew;
            }
            double v = (double)__shfl_sync(0xffffffffu, sacc, 0) +
                       (double)__shfl_sync(0xffffffffu, cacc, 0);
            if (v > best || (v == best && e < besti)) { best = v; besti = e; }
        }
        if (lane == 0) { bv[wid] = best; bi[wid] = besti; }
        __syncthreads();
        if (threadIdx.x == 0) {
            double m = bv[0]; int am = bi[0];
            for (int w = 1; w < 8; w++)
                if (bv[w] > m || (bv[w] == m && bi[w] < am)) { m = bv[w]; am = bi[w]; }
            int old = g_indices[t];
            if (am != old) {
                int blk = t / BT;
                atomicSub(&g_blockCounts[blk * EXPERTS + old], 1);
                atomicAdd(&g_blockCounts[blk * EXPERTS + am], 1);
                g_indices[t] = am;
                out[1 + t] = (float)am;
            }
            float den = 0.0f;
            for (int e = 0; e < EXPERTS; e++) den += __expf(Lsm[e] - mx32);
            out[1 + 2 * T + t] = __expf(Lsm[am] - mx32) / den;
        }
        __syncthreads();
    }
}

// ---------------- pass 3: scan + l_aux (smem-staged) ----------------
__global__ __launch_bounds__(1024) void gate_scan(float* __restrict__ out,
                                                  int T, int nB) {
    __shared__ int   cnt[NB * EXPERTS];      // 32 KB
    __shared__ float red[EXPERTS];
    const int tid = threadIdx.x;

    // parallel coalesced stage-in
#pragma unroll
    for (int q = 0; q < (NB * EXPERTS) / 1024; q++)
        cnt[q * 1024 + tid] = g_blockCounts[q * 1024 + tid];
    __syncthreads();

    if (tid < EXPERTS) {
        const int e = tid;
        int run = 0;
        for (int b = 0; b < nB; b++) {
            g_blockOffsets[b * EXPERTS + e] = run;   // fire-and-forget store
            run += cnt[b * EXPERTS + e];
        }
        red[e] = g_me[e] * (float)run;
    }
    __syncthreads();
    if (tid < EXPERTS) {
        for (int s = EXPERTS / 2; s > 0; s >>= 1) {
            if (tid < s) red[tid] += red[tid + s];
            __syncwarp(0xffffffffu);
            if (s > 32) __syncthreads();
        }
        if (tid == 0)
            out[0] = red[0] * ((float)EXPERTS / ((float)T * (float)T));
    }
}

// ---------------- pass 4: per-token location ----------------
__global__ void gate_loc(float* __restrict__ out, int T) {
    __shared__ int w0cnt[EXPERTS];
    const int b = blockIdx.x;
    const int t = threadIdx.x;
    const int gt = b * BT + t;
    const int e = g_indices[gt];
    const int lane = t & 31;
    const int warp = t >> 5;

    w0cnt[t] = 0;
    __syncthreads();

    unsigned peers = __match_any_sync(0xffffffffu, e);
    int rank = __popc(peers & ((1u << lane) - 1u));
    if (warp == 0 && lane == (__ffs(peers) - 1))
        w0cnt[e] = __popc(peers);
    __syncthreads();

    int loc = g_blockOffsets[b * EXPERTS + e] + rank + (warp ? w0cnt[e] : 0);
    out[1 + T + gt] = (float)loc;
}

// ---------------- launch ----------------
extern "C" void kernel_launch(void* const* d_in, const int* in_sizes, int n_in,
                              void* d_out, int out_size) {
    const float* A = (const float*)d_in[0];
    const float* W = (const float*)d_in[1];
    float* out = (float*)d_out;
    const int T = in_sizes[0] / DIM;        // 8192

    cudaFuncSetAttribute(gemm_kernel, cudaFuncAttributeMaxDynamicSharedMemorySize,
                         SMEM_BYTES);

    wsplit_kernel<<<(EXPERTS * (DIM / 2) + 255) / 256, 256>>>(W);
    gemm_kernel<<<T / MB, GTH, SMEM_BYTES>>>(A, out, T);
    rescue_kernel<<<128, 256>>>(A, W, out, T);
    gate_scan<<<1, 1024>>>(out, T, T / BT);
    gate_loc<<<T / BT, BT>>>(out, T);
}

// round 10
// speedup vs baseline: 1.4686x; 1.4686x over previous
#include <cuda_runtime.h>
#include <cuda_fp16.h>
#include <cstdint>

// ---------------- problem constants ----------------
#define DIM      4096
#define EXPERTS  64
#define T_TOK    8192
#define MB       64                  // tokens per GEMM block
#define BK       128                 // k per stage
#define NSTAGE   (DIM / BK)          // 32
#define GTH      256                 // 8 warps
#define BT       64
#define NB       (T_TOK / BT)        // 128
#define SUSCAP   2048
#define EPS_GAP  1e-5f

// smem layout in uint32 units (fp16x2 packed), USTR=68 -> conflict-free frags
#define USTR     68
#define OFFU_AH  0
#define OFFU_AM  4352                // 64*68
#define OFFU_WH  8704
#define OFFU_WM  13056
#define BUFU     17408
#define SMEM_BYTES (2 * BUFU * 4)    // 139264 B

// ---------------- device scratch ----------------
__device__ float    g_logits[T_TOK * EXPERTS];
__device__ uint32_t g_wh[EXPERTS * (DIM / 2)];   // W hi split, fp16x2
__device__ uint32_t g_wm[EXPERTS * (DIM / 2)];   // W mid split, fp16x2
__device__ float    g_me[EXPERTS];
__device__ int      g_indices[T_TOK];
__device__ int      g_blockCounts[NB * EXPERTS];
__device__ int      g_blockOffsets[NB * EXPERTS];
__device__ int      g_nsus;
__device__ int      g_suspects[SUSCAP];

// ---------------- helpers ----------------
__device__ __forceinline__ uint32_t smem_u32(const void* p) {
    uint32_t a;
    asm("{ .reg .u64 t; cvta.to.shared.u64 t, %1; cvt.u32.u64 %0, t; }" : "=r"(a) : "l"(p));
    return a;
}
__device__ __forceinline__ void split_f16x2(float x0, float x1,
                                            uint32_t& h, uint32_t& m) {
    __half2 h2 = __floats2half2_rn(x0, x1);
    h = *reinterpret_cast<uint32_t*>(&h2);
    float r0 = x0 - __low2float(h2);
    float r1 = x1 - __high2float(h2);
    __half2 m2 = __floats2half2_rn(r0, r1);
    m = *reinterpret_cast<uint32_t*>(&m2);
}
__device__ __forceinline__ void cp16(uint32_t saddr, const void* g) {
    asm volatile("cp.async.cg.shared.global [%0], [%1], 16;" :: "r"(saddr), "l"(g));
}
#define CP_COMMIT() asm volatile("cp.async.commit_group;" ::: "memory")
#define CP_WAIT0()  asm volatile("cp.async.wait_group 0;" ::: "memory")

#define MMA_FP16(d, a, b0, b1)                                               \
    asm volatile(                                                            \
        "mma.sync.aligned.m16n8k16.row.col.f32.f16.f16.f32 "                 \
        "{%0,%1,%2,%3}, {%4,%5,%6,%7}, {%8,%9}, {%0,%1,%2,%3};"              \
        : "+f"((d)[0]), "+f"((d)[1]), "+f"((d)[2]), "+f"((d)[3])             \
        : "r"((a)[0]), "r"((a)[1]), "r"((a)[2]), "r"((a)[3]),                \
          "r"(b0), "r"(b1))

// ---------------- pass 0: W split precompute + init ----------------
__global__ void wsplit_kernel(const float* __restrict__ W) {
    int i = blockIdx.x * blockDim.x + threadIdx.x;   // pair index
    if (i < EXPERTS * (DIM / 2)) {
        float2 x = reinterpret_cast<const float2*>(W)[i];
        uint32_t h, m;
        split_f16x2(x.x, x.y, h, m);
        g_wh[i] = h;
        g_wm[i] = m;
    }
    if (i < EXPERTS) g_me[i] = 0.0f;
    if (i == 0) g_nsus = 0;
}

// ---------------- pass 1: fp16-split GEMM + fused gate epilogue -------------
#define ESTR 65
__global__ __launch_bounds__(GTH, 1) void gemm_kernel(
    const float* __restrict__ A, float* __restrict__ out, int T)
{
    extern __shared__ __align__(16) uint32_t smu[];
    const uint32_t sbase = smem_u32(smu);
    const int tid  = threadIdx.x;
    const int lane = tid & 31;
    const int wid  = tid >> 5;       // 8 warps
    const int wm   = wid >> 1;       // 0..3 : 16-token group
    const int wn   = wid & 1;        // 0..1 : 32-expert group
    const int t0   = blockIdx.x * MB;

    float accP[4][4], accQ[4][4];
#pragma unroll
    for (int ni = 0; ni < 4; ni++)
#pragma unroll
        for (int r = 0; r < 4; r++) { accP[ni][r] = 0.0f; accQ[ni][r] = 0.0f; }

    // prologue: A regs stage 0, W cp.async stage 0
    float4 pA[8];
#pragma unroll
    for (int q = 0; q < 8; q++) {
        int f4 = q * GTH + tid;
        int row = f4 >> 5, c = (f4 & 31) * 4;
        pA[q] = *reinterpret_cast<const float4*>(&A[(size_t)(t0 + row) * DIM + c]);
    }
#pragma unroll
    for (int q = 0; q < 4; q++) {
        int f = q * GTH + tid;               // 0..1023
        int row = f >> 4, c4 = (f & 15) * 4; // uint32 col
        cp16(sbase + (OFFU_WH + row * USTR + c4) * 4, &g_wh[row * (DIM / 2) + c4]);
        cp16(sbase + (OFFU_WM + row * USTR + c4) * 4, &g_wm[row * (DIM / 2) + c4]);
    }
    CP_COMMIT();

    for (int s = 0; s < NSTAGE; s++) {
        uint32_t* buf = smu + (s & 1) * BUFU;
        CP_WAIT0();

        // split-store A tile (fp16 hi/mid)
#pragma unroll
        for (int q = 0; q < 8; q++) {
            int f4 = q * GTH + tid;
            int row = f4 >> 5, c = (f4 & 31) * 2;    // uint32 col
            uint2 h, m;
            split_f16x2(pA[q].x, pA[q].y, h.x, m.x);
            split_f16x2(pA[q].z, pA[q].w, h.y, m.y);
            *reinterpret_cast<uint2*>(&buf[OFFU_AH + row * USTR + c]) = h;
            *reinterpret_cast<uint2*>(&buf[OFFU_AM + row * USTR + c]) = m;
        }
        __syncthreads();

        // prefetch stage s+1
        if (s + 1 < NSTAGE) {
            const int k0 = (s + 1) * BK;
#pragma unroll
            for (int q = 0; q < 8; q++) {
                int f4 = q * GTH + tid;
                int row = f4 >> 5, c = (f4 & 31) * 4;
                pA[q] = *reinterpret_cast<const float4*>(&A[(size_t)(t0 + row) * DIM + k0 + c]);
            }
            uint32_t nb = sbase + ((s + 1) & 1) * BUFU * 4;
            const int ku = k0 / 2;
#pragma unroll
            for (int q = 0; q < 4; q++) {
                int f = q * GTH + tid;
                int row = f >> 4, c4 = (f & 15) * 4;
                cp16(nb + (OFFU_WH + row * USTR + c4) * 4, &g_wh[row * (DIM / 2) + ku + c4]);
                cp16(nb + (OFFU_WM + row * USTR + c4) * 4, &g_wm[row * (DIM / 2) + ku + c4]);
            }
            CP_COMMIT();
        }

        // compute: 8 k16 steps
#pragma unroll
        for (int q = 0; q < 8; q++) {
            const int cu = q * 8 + (lane & 3);
            const int r  = wm * 16 + (lane >> 2);
            uint32_t aH[4], aM[4];
            {
                int b0 = OFFU_AH + r * USTR + cu;
                aH[0] = buf[b0];
                aH[1] = buf[b0 + 8 * USTR];
                aH[2] = buf[b0 + 4];
                aH[3] = buf[b0 + 8 * USTR + 4];
                int b1 = OFFU_AM + r * USTR + cu;
                aM[0] = buf[b1];
                aM[1] = buf[b1 + 8 * USTR];
                aM[2] = buf[b1 + 4];
                aM[3] = buf[b1 + 8 * USTR + 4];
            }
#pragma unroll
            for (int ni = 0; ni < 4; ni++) {
                int n = wn * 32 + ni * 8 + (lane >> 2);
                int bb = n * USTR + cu;
                uint32_t bh0 = buf[OFFU_WH + bb], bh1 = buf[OFFU_WH + bb + 4];
                uint32_t bm0 = buf[OFFU_WM + bb], bm1 = buf[OFFU_WM + bb + 4];
                MMA_FP16(accP[ni], aH, bh0, bh1);
                MMA_FP16(accQ[ni], aH, bm0, bm1);
                MMA_FP16(accQ[ni], aM, bh0, bh1);
            }
        }
    }

    // ---- fused epilogue ----
    __syncthreads();                       // everyone done reading buffers
    float* epi = reinterpret_cast<float*>(smu);      // [64][65]
#pragma unroll
    for (int ni = 0; ni < 4; ni++) {
        int r0 = wm * 16 + (lane >> 2);
        int c0 = wn * 32 + ni * 8 + (lane & 3) * 2;
        float v0 = accP[ni][0] + accQ[ni][0];
        float v1 = accP[ni][1] + accQ[ni][1];
        float v2 = accP[ni][2] + accQ[ni][2];
        float v3 = accP[ni][3] + accQ[ni][3];
        epi[r0 * ESTR + c0]           = v0;
        epi[r0 * ESTR + c0 + 1]       = v1;
        epi[(r0 + 8) * ESTR + c0]     = v2;
        epi[(r0 + 8) * ESTR + c0 + 1] = v3;
        *reinterpret_cast<float2*>(&g_logits[(size_t)(t0 + r0) * EXPERTS + c0]) =
            make_float2(v0, v1);
        *reinterpret_cast<float2*>(&g_logits[(size_t)(t0 + r0 + 8) * EXPERTS + c0]) =
            make_float2(v2, v3);
    }
    __shared__ float ms[MB];
    __shared__ float sums[MB];
    __shared__ int   cnt_s[EXPERTS];
    if (tid < EXPERTS) cnt_s[tid] = 0;
    __syncthreads();

    if (tid < MB) {
        const int t = tid;
        float m = epi[t * ESTR + 0];
        float m2 = -3.4e38f;
        int am = 0;
#pragma unroll 4
        for (int e = 1; e < EXPERTS; e++) {
            float v = epi[t * ESTR + e];
            if (v > m) { m2 = m; m = v; am = e; }
            else if (v > m2) { m2 = v; }
        }
        float ssum = 0.0f;
#pragma unroll 4
        for (int e = 0; e < EXPERTS; e++)
            ssum += __expf(epi[t * ESTR + e] - m);
        ms[t] = m;
        sums[t] = ssum;
        int gt = t0 + t;
        g_indices[gt]       = am;
        out[1 + gt]         = (float)am;
        out[1 + 2 * T + gt] = 1.0f / ssum;
        atomicAdd(&cnt_s[am], 1);
        if (m - m2 < EPS_GAP) {
            int i = atomicAdd(&g_nsus, 1);
            if (i < SUSCAP) g_suspects[i] = gt;
        }
    }
    __syncthreads();

    if (tid < EXPERTS) {
        const int e = tid;
        float accm = 0.0f;
#pragma unroll 4
        for (int t = 0; t < MB; t++)
            accm += __expf(epi[t * ESTR + e] - ms[t]) / sums[t];
        atomicAdd(&g_me[e], accm);
        g_blockCounts[blockIdx.x * EXPERTS + e] = cnt_s[e];
    }
}

// ---------------- pass 2: double-single rescue (adjusts counts) --------------
__device__ __forceinline__ void two_sum(float a, float b, float& s, float& e) {
    s = a + b;
    float bb = s - a;
    e = (a - (s - bb)) + (b - bb);
}

__global__ void rescue_kernel(const float* __restrict__ A,
                              const float* __restrict__ W,
                              float* __restrict__ out, int T) {
    __shared__ float Lsm[EXPERTS];
    __shared__ double bv[8];
    __shared__ int    bi[8];
    const int wid = threadIdx.x >> 5;   // 8 warps
    const int lane = threadIdx.x & 31;
    int n = g_nsus;
    if (n > SUSCAP) n = SUSCAP;

    for (int s = blockIdx.x; s < n; s += gridDim.x) {
        const int t = g_suspects[s];
        const float* ap = A + (size_t)t * DIM;

        if (threadIdx.x < EXPERTS)
            Lsm[threadIdx.x] = g_logits[(size_t)t * EXPERTS + threadIdx.x];
        __syncthreads();
        float mx32 = Lsm[0];
        for (int e = 1; e < EXPERTS; e++) mx32 = fmaxf(mx32, Lsm[e]);
        const float win = mx32 - 2.0f * EPS_GAP;

        double best = -1e300;
        int besti = EXPERTS;
#pragma unroll 1
        for (int sub = 0; sub < 8; sub++) {
            const int e = wid * 8 + sub;
            if (Lsm[e] < win) continue;
            const float* wp = W + (size_t)e * DIM;
            float sacc = 0.0f, cacc = 0.0f;
#pragma unroll 4
            for (int i = 0; i < DIM / 128; i++) {
                int k = (i * 32 + lane) * 4;
                float4 av = *reinterpret_cast<const float4*>(ap + k);
                float4 wv = *reinterpret_cast<const float4*>(wp + k);
#pragma unroll
                for (int j = 0; j < 4; j++) {
                    float a = (&av.x)[j], b = (&wv.x)[j];
                    float p = a * b;
                    float pe = fmaf(a, b, -p);
                    float tnew, err;
                    two_sum(sacc, p, tnew, err);
                    cacc += err + pe;
                    sacc = tnew;
                }
            }
#pragma unroll
            for (int o = 16; o; o >>= 1) {
                float sh = __shfl_down_sync(0xffffffffu, sacc, o);
                float ch = __shfl_down_sync(0xffffffffu, cacc, o);
                float tnew, err;
                two_sum(sacc, sh, tnew, err);
                cacc += ch + err;
                sacc = tnew;
            }
            double v = (double)__shfl_sync(0xffffffffu, sacc, 0) +
                       (double)__shfl_sync(0xffffffffu, cacc, 0);
            if (v > best || (v == best && e < besti)) { best = v; besti = e; }
        }
        if (lane == 0) { bv[wid] = best; bi[wid] = besti; }
        __syncthreads();
        if (threadIdx.x == 0) {
            double m = bv[0]; int am = bi[0];
            for (int w = 1; w < 8; w++)
                if (bv[w] > m || (bv[w] == m && bi[w] < am)) { m = bv[w]; am = bi[w]; }
            int old = g_indices[t];
            if (am != old) {
                int blk = t / BT;
                atomicSub(&g_blockCounts[blk * EXPERTS + old], 1);
                atomicAdd(&g_blockCounts[blk * EXPERTS + am], 1);
                g_indices[t] = am;
                out[1 + t] = (float)am;
            }
            float den = 0.0f;
            for (int e = 0; e < EXPERTS; e++) den += __expf(Lsm[e] - mx32);
            out[1 + 2 * T + t] = __expf(Lsm[am] - mx32) / den;
        }
        __syncthreads();
    }
}

// ---------------- pass 3: scan + l_aux (smem-staged) ----------------
__global__ __launch_bounds__(1024) void gate_scan(float* __restrict__ out,
                                                  int T, int nB) {
    __shared__ int   cnt[NB * EXPERTS];      // 32 KB
    __shared__ float red[EXPERTS];
    const int tid = threadIdx.x;

#pragma unroll
    for (int q = 0; q < (NB * EXPERTS) / 1024; q++)
        cnt[q * 1024 + tid] = g_blockCounts[q * 1024 + tid];
    __syncthreads();

    if (tid < EXPERTS) {
        const int e = tid;
        int run = 0;
        for (int b = 0; b < nB; b++) {
            g_blockOffsets[b * EXPERTS + e] = run;
            run += cnt[b * EXPERTS + e];
        }
        red[e] = g_me[e] * (float)run;
    }
    __syncthreads();
    if (tid < EXPERTS) {
        for (int s = EXPERTS / 2; s > 0; s >>= 1) {
            if (tid < s) red[tid] += red[tid + s];
            __syncwarp(0xffffffffu);
            if (s > 32) __syncthreads();
        }
        if (tid == 0)
            out[0] = red[0] * ((float)EXPERTS / ((float)T * (float)T));
    }
}

// ---------------- pass 4: per-token location ----------------
__global__ void gate_loc(float* __restrict__ out, int T) {
    __shared__ int w0cnt[EXPERTS];
    const int b = blockIdx.x;
    const int t = threadIdx.x;
    const int gt = b * BT + t;
    const int e = g_indices[gt];
    const int lane = t & 31;
    const int warp = t >> 5;

    w0cnt[t] = 0;
    __syncthreads();

    unsigned peers = __match_any_sync(0xffffffffu, e);
    int rank = __popc(peers & ((1u << lane) - 1u));
    if (warp == 0 && lane == (__ffs(peers) - 1))
        w0cnt[e] = __popc(peers);
    __syncthreads();

    int loc = g_blockOffsets[b * EXPERTS + e] + rank + (warp ? w0cnt[e] : 0);
    out[1 + T + gt] = (float)loc;
}

// ---------------- launch ----------------
extern "C" void kernel_launch(void* const* d_in, const int* in_sizes, int n_in,
                              void* d_out, int out_size) {
    const float* A = (const float*)d_in[0];
    const float* W = (const float*)d_in[1];
    float* out = (float*)d_out;
    const int T = in_sizes[0] / DIM;        // 8192

    cudaFuncSetAttribute(gemm_kernel, cudaFuncAttributeMaxDynamicSharedMemorySize,
                         SMEM_BYTES);

    wsplit_kernel<<<(EXPERTS * (DIM / 2) + 255) / 256, 256>>>(W);
    gemm_kernel<<<T / MB, GTH, SMEM_BYTES>>>(A, out, T);
    rescue_kernel<<<128, 256>>>(A, W, out, T);
    gate_scan<<<1, 1024>>>(out, T, T / BT);
    gate_loc<<<T / BT, BT>>>(out, T);
}